// round 11
// baseline (speedup 1.0000x reference)
#include <cuda_runtime.h>
#include <cuda_fp16.h>
#include <cstdint>

#define BB 8
#define SS 1024
#define DD 512
#define HH 8
#define DHH 64
#define MTOT (BB*SS)   // 8192
#define BH   (BB*HH)   // 64

// ---------------- scratch (__device__ globals) ---------------------------------
__device__ __half g_qu[MTOT*DD];                // scale*(q + u_bias)  (fp16)
__device__ __half g_qv[MTOT*DD];                // scale*(q + v_bias)  (fp16)
__device__ __half g_k [MTOT*DD];
__device__ __half g_v [MTOT*DD];
__device__ __half g_p [MTOT*DD];
__device__ float  g_M [BH*SS*SS];               // PRE-SHIFTED pos scores (fp32)
__device__ float  g_ctx[MTOT*DD];

// ---------------- helpers -------------------------------------------------------
__device__ __forceinline__ uint32_t h2u(float a, float b) {
    __half2 h = __floats2half2_rn(a, b);
    return *reinterpret_cast<uint32_t*>(&h);
}
__device__ __forceinline__ uint4 pack8(float4 a, float4 b) {
    uint4 r;
    r.x = h2u(a.x, a.y); r.y = h2u(a.z, a.w);
    r.z = h2u(b.x, b.y); r.w = h2u(b.z, b.w);
    return r;
}
__device__ __forceinline__ void ldsm4(uint32_t* r, const __half* p) {
    uint32_t a = (uint32_t)__cvta_generic_to_shared(p);
    asm volatile("ldmatrix.sync.aligned.m8n8.x4.shared.b16 {%0,%1,%2,%3}, [%4];"
                 : "=r"(r[0]), "=r"(r[1]), "=r"(r[2]), "=r"(r[3]) : "r"(a));
}
__device__ __forceinline__ void ldsm4t(uint32_t* r, const __half* p) {
    uint32_t a = (uint32_t)__cvta_generic_to_shared(p);
    asm volatile("ldmatrix.sync.aligned.m8n8.x4.trans.shared.b16 {%0,%1,%2,%3}, [%4];"
                 : "=r"(r[0]), "=r"(r[1]), "=r"(r[2]), "=r"(r[3]) : "r"(a));
}
__device__ __forceinline__ void mma_f16(float c[4], const uint32_t a[4],
                                        uint32_t b0, uint32_t b1)
{
    asm volatile(
        "mma.sync.aligned.m16n8k16.row.col.f32.f16.f16.f32 "
        "{%0,%1,%2,%3}, {%4,%5,%6,%7}, {%8,%9}, {%0,%1,%2,%3};"
        : "+f"(c[0]), "+f"(c[1]), "+f"(c[2]), "+f"(c[3])
        : "r"(a[0]), "r"(a[1]), "r"(a[2]), "r"(a[3]), "r"(b0), "r"(b1));
}
__device__ __forceinline__ void cpa16(__half* dst, const __half* src) {
    uint32_t d = (uint32_t)__cvta_generic_to_shared(dst);
    asm volatile("cp.async.ca.shared.global [%0], [%1], 16;" :: "r"(d), "l"(src));
}
#define CPA_COMMIT() asm volatile("cp.async.commit_group;")
#define CPA_WAIT0()  asm volatile("cp.async.wait_group 0;")

// ---------------- kernel 1: projection GEMM (fp16 MMA, merged) ------------------
struct ProjSet {
    const float *A, *W, *bias, *ex0, *ex1;
    void *out0, *out1;     // __half* if h_out else float*
    int h_out;
    float post;            // post-multiplier applied to out0/out1 values
};
struct ProjArgs { ProjSet s[4]; };

#define BFS 136   // W tile row stride in halves

__global__ void __launch_bounds__(256, 2)
proj_kernel(ProjArgs args)
{
    __shared__ __half Af[128 * 40];    // A tile [m][k]
    __shared__ __half Bf[32 * BFS];    // W tile [k][n], n = 128
    const ProjSet ps = args.s[blockIdx.z];
    const float* __restrict__ A = ps.A;
    const float* __restrict__ W = ps.W;

    const int tid  = threadIdx.x;
    const int lane = tid & 31, w = tid >> 5;
    const int wm = w & 1, wn = w >> 1;            // 2 x 4 warps, warp tile 64x32
    const int m_w = wm * 64, n_w = wn * 32;
    const int m0 = blockIdx.y * 128, n0 = blockIdx.x * 128;
    const int lq = lane >> 2, lr = lane & 3;
    const int aR = ((lane >> 3) & 1) * 8 + (lane & 7);
    const int aK = (lane >> 4) * 8;

    const int a_r = tid >> 2, a_c = (tid & 3) * 8;     // A: rows +t*64
    const int b_r = tid >> 4, b_c = (tid & 15) * 8;    // W: rows +t*16

    float4 pa[2][2], pb[2][2];
#pragma unroll
    for (int t = 0; t < 2; t++) {
        const float* p = &A[(size_t)(m0 + a_r + t * 64) * DD + a_c];
        pa[t][0] = *(const float4*)p; pa[t][1] = *(const float4*)(p + 4);
        const float* q = &W[(size_t)(b_r + t * 16) * DD + n0 + b_c];
        pb[t][0] = *(const float4*)q; pb[t][1] = *(const float4*)(q + 4);
    }

    float acc[4][4][4] = {};

    for (int k0 = 0; k0 < DD; k0 += 32) {
#pragma unroll
        for (int t = 0; t < 2; t++)
            *(uint4*)&Af[(a_r + t * 64) * 40 + a_c] = pack8(pa[t][0], pa[t][1]);
#pragma unroll
        for (int t = 0; t < 2; t++)
            *(uint4*)&Bf[(b_r + t * 16) * BFS + b_c] = pack8(pb[t][0], pb[t][1]);
        __syncthreads();
        if (k0 + 32 < DD) {
#pragma unroll
            for (int t = 0; t < 2; t++) {
                const float* p = &A[(size_t)(m0 + a_r + t * 64) * DD + k0 + 32 + a_c];
                pa[t][0] = *(const float4*)p; pa[t][1] = *(const float4*)(p + 4);
                const float* q = &W[(size_t)(k0 + 32 + b_r + t * 16) * DD + n0 + b_c];
                pb[t][0] = *(const float4*)q; pb[t][1] = *(const float4*)(q + 4);
            }
        }
#pragma unroll
        for (int kb = 0; kb < 2; kb++) {
            uint32_t a[4][4], bb[2][4];
#pragma unroll
            for (int ma = 0; ma < 4; ma++)
                ldsm4(a[ma], &Af[(m_w + ma * 16 + aR) * 40 + kb * 16 + aK]);
#pragma unroll
            for (int np = 0; np < 2; np++)
                ldsm4t(bb[np], &Bf[(kb * 16 + aR) * BFS + n_w + np * 16 + aK]);
#pragma unroll
            for (int ma = 0; ma < 4; ma++)
#pragma unroll
                for (int an = 0; an < 4; an++)
                    mma_f16(acc[ma][an], a[ma],
                            bb[an >> 1][(an & 1) * 2], bb[an >> 1][(an & 1) * 2 + 1]);
        }
        __syncthreads();
    }

#pragma unroll
    for (int ma = 0; ma < 4; ma++) {
#pragma unroll
        for (int an = 0; an < 4; an++) {
#pragma unroll
            for (int half = 0; half < 2; half++) {
                int row = m0 + m_w + ma * 16 + lq + half * 8;
                int col = n0 + n_w + an * 8 + lr * 2;
                float v0 = acc[ma][an][half * 2 + 0];
                float v1 = acc[ma][an][half * 2 + 1];
                if (ps.bias) { v0 += ps.bias[col]; v1 += ps.bias[col + 1]; }
                if (ps.out0) {
                    float e0 = ps.ex0 ? ps.ex0[col] : 0.f;
                    float e1 = ps.ex0 ? ps.ex0[col + 1] : 0.f;
                    float o0 = (v0 + e0) * ps.post, o1 = (v1 + e1) * ps.post;
                    if (ps.h_out)
                        *(uint32_t*)&((__half*)ps.out0)[(size_t)row * DD + col] = h2u(o0, o1);
                    else
                        *(float2*)&((float*)ps.out0)[(size_t)row * DD + col] =
                            make_float2(o0, o1);
                }
                if (ps.out1) {
                    float e0 = ps.ex1 ? ps.ex1[col] : 0.f;
                    float e1 = ps.ex1 ? ps.ex1[col + 1] : 0.f;
                    *(uint32_t*)&((__half*)ps.out1)[(size_t)row * DD + col] =
                        h2u((v0 + e0) * ps.post, (v1 + e1) * ps.post);
                }
            }
        }
    }
}

// ---------------- kernel 2: pos-score GEMM, SHIFTED write -----------------------
// Computes M[i,k] = qv_i . p_k and scatters each element to its Transformer-XL
// shifted position:  k >= S-1-i -> Shift[i, k-S+1+i];  else (i>0) -> Shift[i-1, k+i+1].
// (Bijection onto Shift minus the c=i+1 hole, which fa zero-selects.)
__global__ void __launch_bounds__(256, 2)
score_kernel(const __half* __restrict__ Qm, const __half* __restrict__ Km,
             float* __restrict__ Out)
{
    __shared__ __half Qf[128 * 72];    // [i][d]
    __shared__ __half Pf[128 * 72];    // [j][d]
    const int tid  = threadIdx.x;
    const int lane = tid & 31, w = tid >> 5;
    const int wm = w & 1, wn = w >> 1;
    const int m_w = wm * 64, n_w = wn * 32;
    const int z = blockIdx.z, b = z >> 3, h = z & 7;
    const int i0 = blockIdx.y * 128, j0 = blockIdx.x * 128;
    const int lq = lane >> 2, lr = lane & 3;
    const int aR = ((lane >> 3) & 1) * 8 + (lane & 7);
    const int aK = (lane >> 4) * 8;
    const int bR = (lane >> 4) * 8 + (lane & 7);
    const int bK = ((lane >> 3) & 1) * 8;
    const __half* Qb = Qm + (size_t)(b * SS) * DD + h * DHH;
    const __half* Kb = Km + (size_t)(b * SS) * DD + h * DHH;

#pragma unroll
    for (int t = 0; t < 4; t++) {
        int id = tid + t * 256;
        int row = id >> 3, col = (id & 7) * 8;
        *(uint4*)&Qf[row * 72 + col] = *(const uint4*)&Qb[(size_t)(i0 + row) * DD + col];
        *(uint4*)&Pf[row * 72 + col] = *(const uint4*)&Kb[(size_t)(j0 + row) * DD + col];
    }
    __syncthreads();

    float acc[4][4][4] = {};
#pragma unroll
    for (int kb = 0; kb < 4; kb++) {
        uint32_t a[4][4], bb[2][4];
#pragma unroll
        for (int ma = 0; ma < 4; ma++)
            ldsm4(a[ma], &Qf[(m_w + ma * 16 + aR) * 72 + kb * 16 + aK]);
#pragma unroll
        for (int np = 0; np < 2; np++)
            ldsm4(bb[np], &Pf[(n_w + np * 16 + bR) * 72 + kb * 16 + bK]);
#pragma unroll
        for (int ma = 0; ma < 4; ma++)
#pragma unroll
            for (int an = 0; an < 4; an++)
                mma_f16(acc[ma][an], a[ma],
                        bb[an >> 1][(an & 1) * 2], bb[an >> 1][(an & 1) * 2 + 1]);
    }

    float* Oz = Out + (size_t)z * SS * SS;
#pragma unroll
    for (int ma = 0; ma < 4; ma++) {
#pragma unroll
        for (int an = 0; an < 4; an++) {
#pragma unroll
            for (int half = 0; half < 2; half++) {
#pragma unroll
                for (int e = 0; e < 2; e++) {
                    int row = i0 + m_w + ma * 16 + lq + half * 8;
                    int col = j0 + n_w + an * 8 + lr * 2 + e;
                    float v = acc[ma][an][half * 2 + e];
                    if (col >= SS - 1 - row)
                        Oz[(size_t)row * SS + (col - SS + 1 + row)] = v;
                    else if (row > 0)
                        Oz[(size_t)(row - 1) * SS + (col + row + 1)] = v;
                }
            }
        }
    }
}

// ---------------- kernel 3: fused QK^T + softmax + PV ---------------------------
// 128 thr = 4 warps; block owns 64 q-rows. cp.async double-buffered K/V.
// Pos scores are pre-shifted: dense float2 row reads + zero-select at j==r+1.
__global__ void __launch_bounds__(128, 3)
fa_kernel(const __half* __restrict__ Qu, const __half* __restrict__ Km,
          const float* __restrict__ M, const __half* __restrict__ V,
          float* __restrict__ Ctx)
{
    __shared__ __half Qf[64 * 72];
    __shared__ __half Kf[2][64 * 72];
    __shared__ __half Vf[2][64 * 72];

    const int tid  = threadIdx.x;
    const int lane = tid & 31, w = tid >> 5;
    const int lq = lane >> 2, lr = lane & 3;
    const int aR = ((lane >> 3) & 1) * 8 + (lane & 7);
    const int aK = (lane >> 4) * 8;
    const int bR = (lane >> 4) * 8 + (lane & 7);
    const int bK = ((lane >> 3) & 1) * 8;
    const int z = blockIdx.y, b = z >> 3, h = z & 7;
    const int i0 = blockIdx.x * 64;
    const int r0 = i0 + w * 16 + lq;
    const int r1 = r0 + 8;

    const __half* Qb = Qu + ((size_t)(b * SS) + i0) * DD + h * DHH;
    const __half* Kb = Km + (size_t)(b * SS) * DD + h * DHH;
    const __half* Vb = V  + (size_t)(b * SS) * DD + h * DHH;
    const float* Srow0 = M + ((size_t)z * SS + r0) * SS;
    const float* Srow1 = M + ((size_t)z * SS + r1) * SS;

    // initial group: Q + K0 + V0
#pragma unroll
    for (int t = 0; t < 4; t++) {
        int id = tid + t * 128;
        int row = id >> 3, ch = (id & 7) * 8;
        cpa16(&Qf[row * 72 + ch],    &Qb[(size_t)row * DD + ch]);
        cpa16(&Kf[0][row * 72 + ch], &Kb[(size_t)row * DD + ch]);
        cpa16(&Vf[0][row * 72 + ch], &Vb[(size_t)row * DD + ch]);
    }
    CPA_COMMIT();

    float acc[8][4] = {};
    float rm0 = -1e30f, rm1 = -1e30f, l0 = 0.f, l1 = 0.f;
    int buf = 0;

    for (int jt = 0; jt < SS; jt += 64) {
        // dense pre-shifted pos rows (float2), zero hole at j == r+1
        float pv[8][4];
#pragma unroll
        for (int an = 0; an < 8; an++) {
            int j = jt + an * 8 + 2 * lr;
            float2 a0 = *(const float2*)&Srow0[j];
            float2 a1 = *(const float2*)&Srow1[j];
            pv[an][0] = (j     == r0 + 1) ? 0.f : a0.x;
            pv[an][1] = (j + 1 == r0 + 1) ? 0.f : a0.y;
            pv[an][2] = (j     == r1 + 1) ? 0.f : a1.x;
            pv[an][3] = (j + 1 == r1 + 1) ? 0.f : a1.y;
        }

        CPA_WAIT0();
        __syncthreads();           // all warps done with buf^1 reads + copies visible

        // kick off next tile's K/V copy into the other buffer
        if (jt + 64 < SS) {
            int nb = buf ^ 1;
#pragma unroll
            for (int t = 0; t < 4; t++) {
                int id = tid + t * 128;
                int row = id >> 3, ch = (id & 7) * 8;
                cpa16(&Kf[nb][row * 72 + ch], &Kb[(size_t)(jt + 64 + row) * DD + ch]);
                cpa16(&Vf[nb][row * 72 + ch], &Vb[(size_t)(jt + 64 + row) * DD + ch]);
            }
        }
        CPA_COMMIT();

        // S = (scaled Q) K^T  (warp: 16 rows x 64 j)
        float s[8][4] = {};
#pragma unroll
        for (int kb = 0; kb < 4; kb++) {
            uint32_t a[4], bb[4][4];
            ldsm4(a, &Qf[(w * 16 + aR) * 72 + kb * 16 + aK]);
#pragma unroll
            for (int np = 0; np < 4; np++)
                ldsm4(bb[np], &Kf[buf][(np * 16 + bR) * 72 + kb * 16 + bK]);
#pragma unroll
            for (int an = 0; an < 8; an++)
                mma_f16(s[an], a,
                        bb[an >> 1][(an & 1) * 2], bb[an >> 1][(an & 1) * 2 + 1]);
        }

        // combine with pre-scaled pos scores, tile max
        float tm0 = -1e30f, tm1 = -1e30f;
#pragma unroll
        for (int an = 0; an < 8; an++) {
#pragma unroll
            for (int e = 0; e < 2; e++) {
                float s0 = s[an][e]     + pv[an][e];
                float s1 = s[an][2 + e] + pv[an][2 + e];
                s[an][e] = s0; s[an][2 + e] = s1;
                tm0 = fmaxf(tm0, s0); tm1 = fmaxf(tm1, s1);
            }
        }
        tm0 = fmaxf(tm0, __shfl_xor_sync(0xffffffffu, tm0, 1));
        tm0 = fmaxf(tm0, __shfl_xor_sync(0xffffffffu, tm0, 2));
        tm1 = fmaxf(tm1, __shfl_xor_sync(0xffffffffu, tm1, 1));
        tm1 = fmaxf(tm1, __shfl_xor_sync(0xffffffffu, tm1, 2));

        float nm0 = fmaxf(rm0, tm0), nm1 = fmaxf(rm1, tm1);
        float al0 = __expf(rm0 - nm0), al1 = __expf(rm1 - nm1);
        float sum0 = 0.f, sum1 = 0.f;
#pragma unroll
        for (int an = 0; an < 8; an++)
#pragma unroll
            for (int e = 0; e < 2; e++) {
                s[an][e]     = __expf(s[an][e]     - nm0); sum0 += s[an][e];
                s[an][2 + e] = __expf(s[an][2 + e] - nm1); sum1 += s[an][2 + e];
            }
        sum0 += __shfl_xor_sync(0xffffffffu, sum0, 1);
        sum0 += __shfl_xor_sync(0xffffffffu, sum0, 2);
        sum1 += __shfl_xor_sync(0xffffffffu, sum1, 1);
        sum1 += __shfl_xor_sync(0xffffffffu, sum1, 2);
        l0 = l0 * al0 + sum0; l1 = l1 * al1 + sum1;
        rm0 = nm0; rm1 = nm1;

#pragma unroll
        for (int an = 0; an < 8; an++) {
            acc[an][0] *= al0; acc[an][1] *= al0;
            acc[an][2] *= al1; acc[an][3] *= al1;
        }

        // O += P @ V ; P straight from registers (C-frag == A-frag layout)
#pragma unroll
        for (int jj = 0; jj < 4; jj++) {
            uint32_t a[4];
            a[0] = h2u(s[2*jj][0],     s[2*jj][1]);
            a[1] = h2u(s[2*jj][2],     s[2*jj][3]);
            a[2] = h2u(s[2*jj + 1][0], s[2*jj + 1][1]);
            a[3] = h2u(s[2*jj + 1][2], s[2*jj + 1][3]);
            uint32_t vv[4][4];
#pragma unroll
            for (int dp = 0; dp < 4; dp++)
                ldsm4t(vv[dp], &Vf[buf][(jj * 16 + aR) * 72 + dp * 16 + aK]);
#pragma unroll
            for (int dn = 0; dn < 8; dn++)
                mma_f16(acc[dn], a,
                        vv[dn >> 1][(dn & 1) * 2], vv[dn >> 1][(dn & 1) * 2 + 1]);
        }
        buf ^= 1;
    }

    float inv0 = 1.f / l0, inv1 = 1.f / l1;
#pragma unroll
    for (int dn = 0; dn < 8; dn++) {
        int col = dn * 8 + 2 * lr;
        float2 v0 = make_float2(acc[dn][0] * inv0, acc[dn][1] * inv0);
        float2 v1 = make_float2(acc[dn][2] * inv1, acc[dn][3] * inv1);
        *(float2*)&Ctx[(size_t)(b * SS + r0) * DD + h * DHH + col] = v0;
        *(float2*)&Ctx[(size_t)(b * SS + r1) * DD + h * DHH + col] = v1;
    }
}

// ---------------- launcher ------------------------------------------------------
extern "C" void kernel_launch(void* const* d_in, const int* in_sizes, int n_in,
                              void* d_out, int out_size)
{
    (void)in_sizes; (void)n_in; (void)out_size;
    const float* query = (const float*)d_in[0];
    const float* key   = (const float*)d_in[1];
    const float* value = (const float*)d_in[2];
    const float* pose  = (const float*)d_in[3];
    const float* Wq = (const float*)d_in[4];
    const float* bq = (const float*)d_in[5];
    const float* Wk = (const float*)d_in[6];
    const float* bk = (const float*)d_in[7];
    const float* Wv = (const float*)d_in[8];
    const float* bv = (const float*)d_in[9];
    const float* Wp = (const float*)d_in[10];
    const float* ub = (const float*)d_in[11];
    const float* vb = (const float*)d_in[12];
    const float* Wo = (const float*)d_in[13];
    const float* bo = (const float*)d_in[14];
    float* out = (float*)d_out;

    const float scale = 0.04419417382415922f;   // 1/sqrt(512)

    __half *qu, *qv, *kk, *vv, *pp;
    float *M, *ctx;
    cudaGetSymbolAddress((void**)&qu,  g_qu);
    cudaGetSymbolAddress((void**)&qv,  g_qv);
    cudaGetSymbolAddress((void**)&kk,  g_k);
    cudaGetSymbolAddress((void**)&vv,  g_v);
    cudaGetSymbolAddress((void**)&pp,  g_p);
    cudaGetSymbolAddress((void**)&M,   g_M);
    cudaGetSymbolAddress((void**)&ctx, g_ctx);

    // merged 4 input projections (fp16 outputs; qu/qv pre-scaled)
    ProjArgs pa;
    pa.s[0] = {query, Wq, bq, ub, vb, qu, qv, 1, scale};
    pa.s[1] = {key,   Wk, bk, nullptr, nullptr, kk, nullptr, 1, 1.f};
    pa.s[2] = {value, Wv, bv, nullptr, nullptr, vv, nullptr, 1, 1.f};
    pa.s[3] = {pose,  Wp, nullptr, nullptr, nullptr, pp, nullptr, 1, 1.f};
    dim3 pg(DD / 128, MTOT / 128, 4);      // (4, 64, 4)
    proj_kernel<<<pg, 256>>>(pa);

    dim3 sg(SS / 128, SS / 128, BH);       // (8,8,64)
    score_kernel<<<sg, 256>>>(qv, pp, M);

    dim3 fg(SS / 64, BH);                  // (16, 64)
    fa_kernel<<<fg, 128>>>(qu, kk, M, vv, ctx);

    // output projection (fp32 out)
    ProjArgs po;
    po.s[0] = {ctx, Wo, bo, nullptr, nullptr, out, nullptr, 0, 1.f};
    po.s[1] = po.s[0]; po.s[2] = po.s[0]; po.s[3] = po.s[0];
    dim3 pg1(DD / 128, MTOT / 128, 1);     // (4, 64, 1)
    proj_kernel<<<pg1, 256>>>(po);
}

// round 12
// speedup vs baseline: 1.1843x; 1.1843x over previous
#include <cuda_runtime.h>
#include <cuda_fp16.h>
#include <cstdint>

#define BB 8
#define SS 1024
#define DD 512
#define HH 8
#define DHH 64
#define MTOT (BB*SS)   // 8192
#define BH   (BB*HH)   // 64

// ---------------- scratch (__device__ globals) ---------------------------------
__device__ __half g_qu[MTOT*DD];                // scale*(q + u_bias)  (fp16)
__device__ __half g_qv[MTOT*DD];                // scale*(q + v_bias)  (fp16)
__device__ __half g_k [MTOT*DD];
__device__ __half g_v [MTOT*DD];
__device__ __half g_p [MTOT*DD];
__device__ float  g_M [BH*SS*SS];               // pre-scaled pos scores (fp32, unshifted)
__device__ float  g_ctx[MTOT*DD];

// ---------------- helpers -------------------------------------------------------
__device__ __forceinline__ uint32_t h2u(float a, float b) {
    __half2 h = __floats2half2_rn(a, b);
    return *reinterpret_cast<uint32_t*>(&h);
}
__device__ __forceinline__ uint4 pack8(float4 a, float4 b) {
    uint4 r;
    r.x = h2u(a.x, a.y); r.y = h2u(a.z, a.w);
    r.z = h2u(b.x, b.y); r.w = h2u(b.z, b.w);
    return r;
}
__device__ __forceinline__ void ldsm4(uint32_t* r, const __half* p) {
    uint32_t a = (uint32_t)__cvta_generic_to_shared(p);
    asm volatile("ldmatrix.sync.aligned.m8n8.x4.shared.b16 {%0,%1,%2,%3}, [%4];"
                 : "=r"(r[0]), "=r"(r[1]), "=r"(r[2]), "=r"(r[3]) : "r"(a));
}
__device__ __forceinline__ void ldsm4t(uint32_t* r, const __half* p) {
    uint32_t a = (uint32_t)__cvta_generic_to_shared(p);
    asm volatile("ldmatrix.sync.aligned.m8n8.x4.trans.shared.b16 {%0,%1,%2,%3}, [%4];"
                 : "=r"(r[0]), "=r"(r[1]), "=r"(r[2]), "=r"(r[3]) : "r"(a));
}
__device__ __forceinline__ void mma_f16(float c[4], const uint32_t a[4],
                                        uint32_t b0, uint32_t b1)
{
    asm volatile(
        "mma.sync.aligned.m16n8k16.row.col.f32.f16.f16.f32 "
        "{%0,%1,%2,%3}, {%4,%5,%6,%7}, {%8,%9}, {%0,%1,%2,%3};"
        : "+f"(c[0]), "+f"(c[1]), "+f"(c[2]), "+f"(c[3])
        : "r"(a[0]), "r"(a[1]), "r"(a[2]), "r"(a[3]), "r"(b0), "r"(b1));
}
__device__ __forceinline__ void cpa16(__half* dst, const __half* src) {
    uint32_t d = (uint32_t)__cvta_generic_to_shared(dst);
    asm volatile("cp.async.ca.shared.global [%0], [%1], 16;" :: "r"(d), "l"(src));
}
#define CPA_COMMIT() asm volatile("cp.async.commit_group;")
#define CPA_WAIT0()  asm volatile("cp.async.wait_group 0;")

// ---------------- kernel 1: projection GEMM (fp16 MMA, merged, ping-pong) -------
struct ProjSet {
    const float *A, *W, *bias, *ex0, *ex1;
    void *out0, *out1;     // __half* if h_out else float*
    int h_out;
    float post;            // post-multiplier applied to out0/out1 values
};
struct ProjArgs { ProjSet s[4]; };

#define BFS 136   // W tile row stride in halves

__global__ void __launch_bounds__(256, 2)
proj_kernel(ProjArgs args)
{
    __shared__ __half Af[2][128 * 40];    // A tile [m][k], ping-pong
    __shared__ __half Bf[2][32 * BFS];    // W tile [k][n], n = 128, ping-pong
    const ProjSet ps = args.s[blockIdx.z];
    const float* __restrict__ A = ps.A;
    const float* __restrict__ W = ps.W;

    const int tid  = threadIdx.x;
    const int lane = tid & 31, w = tid >> 5;
    const int wm = w & 1, wn = w >> 1;            // 2 x 4 warps, warp tile 64x32
    const int m_w = wm * 64, n_w = wn * 32;
    const int m0 = blockIdx.y * 128, n0 = blockIdx.x * 128;
    const int lq = lane >> 2, lr = lane & 3;
    const int aR = ((lane >> 3) & 1) * 8 + (lane & 7);
    const int aK = (lane >> 4) * 8;

    const int a_r = tid >> 2, a_c = (tid & 3) * 8;     // A: rows +t*64
    const int b_r = tid >> 4, b_c = (tid & 15) * 8;    // W: rows +t*16

    float4 pa[2][2], pb[2][2];
#pragma unroll
    for (int t = 0; t < 2; t++) {
        const float* p = &A[(size_t)(m0 + a_r + t * 64) * DD + a_c];
        pa[t][0] = *(const float4*)p; pa[t][1] = *(const float4*)(p + 4);
        const float* q = &W[(size_t)(b_r + t * 16) * DD + n0 + b_c];
        pb[t][0] = *(const float4*)q; pb[t][1] = *(const float4*)(q + 4);
    }
    // store tile 0 to buffer 0
#pragma unroll
    for (int t = 0; t < 2; t++)
        *(uint4*)&Af[0][(a_r + t * 64) * 40 + a_c] = pack8(pa[t][0], pa[t][1]);
#pragma unroll
    for (int t = 0; t < 2; t++)
        *(uint4*)&Bf[0][(b_r + t * 16) * BFS + b_c] = pack8(pb[t][0], pb[t][1]);
    __syncthreads();

    float acc[4][4][4] = {};
    int cur = 0;

    for (int k0 = 0; k0 < DD; k0 += 32) {
        const bool has_next = (k0 + 32 < DD);
        if (has_next) {
#pragma unroll
            for (int t = 0; t < 2; t++) {
                const float* p = &A[(size_t)(m0 + a_r + t * 64) * DD + k0 + 32 + a_c];
                pa[t][0] = *(const float4*)p; pa[t][1] = *(const float4*)(p + 4);
                const float* q = &W[(size_t)(k0 + 32 + b_r + t * 16) * DD + n0 + b_c];
                pb[t][0] = *(const float4*)q; pb[t][1] = *(const float4*)(q + 4);
            }
        }
#pragma unroll
        for (int kb = 0; kb < 2; kb++) {
            uint32_t a[4][4], bb[2][4];
#pragma unroll
            for (int ma = 0; ma < 4; ma++)
                ldsm4(a[ma], &Af[cur][(m_w + ma * 16 + aR) * 40 + kb * 16 + aK]);
#pragma unroll
            for (int np = 0; np < 2; np++)
                ldsm4t(bb[np], &Bf[cur][(kb * 16 + aR) * BFS + n_w + np * 16 + aK]);
#pragma unroll
            for (int ma = 0; ma < 4; ma++)
#pragma unroll
                for (int an = 0; an < 4; an++)
                    mma_f16(acc[ma][an], a[ma],
                            bb[an >> 1][(an & 1) * 2], bb[an >> 1][(an & 1) * 2 + 1]);
        }
        if (has_next) {
            int nb = cur ^ 1;
#pragma unroll
            for (int t = 0; t < 2; t++)
                *(uint4*)&Af[nb][(a_r + t * 64) * 40 + a_c] = pack8(pa[t][0], pa[t][1]);
#pragma unroll
            for (int t = 0; t < 2; t++)
                *(uint4*)&Bf[nb][(b_r + t * 16) * BFS + b_c] = pack8(pb[t][0], pb[t][1]);
            __syncthreads();
            cur = nb;
        }
    }

#pragma unroll
    for (int ma = 0; ma < 4; ma++) {
#pragma unroll
        for (int an = 0; an < 4; an++) {
#pragma unroll
            for (int half = 0; half < 2; half++) {
                int row = m0 + m_w + ma * 16 + lq + half * 8;
                int col = n0 + n_w + an * 8 + lr * 2;
                float v0 = acc[ma][an][half * 2 + 0];
                float v1 = acc[ma][an][half * 2 + 1];
                if (ps.bias) { v0 += ps.bias[col]; v1 += ps.bias[col + 1]; }
                if (ps.out0) {
                    float e0 = ps.ex0 ? ps.ex0[col] : 0.f;
                    float e1 = ps.ex0 ? ps.ex0[col + 1] : 0.f;
                    float o0 = (v0 + e0) * ps.post, o1 = (v1 + e1) * ps.post;
                    if (ps.h_out)
                        *(uint32_t*)&((__half*)ps.out0)[(size_t)row * DD + col] = h2u(o0, o1);
                    else
                        *(float2*)&((float*)ps.out0)[(size_t)row * DD + col] =
                            make_float2(o0, o1);
                }
                if (ps.out1) {
                    float e0 = ps.ex1 ? ps.ex1[col] : 0.f;
                    float e1 = ps.ex1 ? ps.ex1[col + 1] : 0.f;
                    *(uint32_t*)&((__half*)ps.out1)[(size_t)row * DD + col] =
                        h2u((v0 + e0) * ps.post, (v1 + e1) * ps.post);
                }
            }
        }
    }
}

// ---------------- kernel 2: pos-score GEMM (M), fp16 in / fp32 out (R10) --------
__global__ void __launch_bounds__(256, 2)
score_kernel(const __half* __restrict__ Qm, const __half* __restrict__ Km,
             float* __restrict__ Out)
{
    __shared__ __half Qf[128 * 72];    // [i][d]
    __shared__ __half Pf[128 * 72];    // [j][d]
    const int tid  = threadIdx.x;
    const int lane = tid & 31, w = tid >> 5;
    const int wm = w & 1, wn = w >> 1;
    const int m_w = wm * 64, n_w = wn * 32;
    const int z = blockIdx.z, b = z >> 3, h = z & 7;
    const int i0 = blockIdx.y * 128, j0 = blockIdx.x * 128;
    const int lq = lane >> 2, lr = lane & 3;
    const int aR = ((lane >> 3) & 1) * 8 + (lane & 7);
    const int aK = (lane >> 4) * 8;
    const int bR = (lane >> 4) * 8 + (lane & 7);
    const int bK = ((lane >> 3) & 1) * 8;
    const __half* Qb = Qm + (size_t)(b * SS) * DD + h * DHH;
    const __half* Kb = Km + (size_t)(b * SS) * DD + h * DHH;

#pragma unroll
    for (int t = 0; t < 4; t++) {
        int id = tid + t * 256;
        int row = id >> 3, col = (id & 7) * 8;
        *(uint4*)&Qf[row * 72 + col] = *(const uint4*)&Qb[(size_t)(i0 + row) * DD + col];
        *(uint4*)&Pf[row * 72 + col] = *(const uint4*)&Kb[(size_t)(j0 + row) * DD + col];
    }
    __syncthreads();

    float acc[4][4][4] = {};
#pragma unroll
    for (int kb = 0; kb < 4; kb++) {
        uint32_t a[4][4], bb[2][4];
#pragma unroll
        for (int ma = 0; ma < 4; ma++)
            ldsm4(a[ma], &Qf[(m_w + ma * 16 + aR) * 72 + kb * 16 + aK]);
#pragma unroll
        for (int np = 0; np < 2; np++)
            ldsm4(bb[np], &Pf[(n_w + np * 16 + bR) * 72 + kb * 16 + bK]);
#pragma unroll
        for (int ma = 0; ma < 4; ma++)
#pragma unroll
            for (int an = 0; an < 4; an++)
                mma_f16(acc[ma][an], a[ma],
                        bb[an >> 1][(an & 1) * 2], bb[an >> 1][(an & 1) * 2 + 1]);
    }

#pragma unroll
    for (int ma = 0; ma < 4; ma++) {
#pragma unroll
        for (int an = 0; an < 4; an++) {
#pragma unroll
            for (int half = 0; half < 2; half++) {
                int row = i0 + m_w + ma * 16 + lq + half * 8;
                int col = j0 + n_w + an * 8 + lr * 2;
                float2 vv = make_float2(acc[ma][an][half * 2 + 0],
                                        acc[ma][an][half * 2 + 1]);
                *(float2*)&Out[((size_t)z * SS + row) * SS + col] = vv;
            }
        }
    }
}

// ---------------- kernel 3: fused QK^T + shift + softmax + PV -------------------
// 256 thr = 8 warps; block owns 128 q-rows (K/V tiles shared by 2x the compute).
// cp.async double-buffered K/V; fp32 banded M prefetch into regs; P in registers.
#define FA_SMEM ((128*72 + 2*64*72 + 2*64*72) * 2)   // bytes (55296)
__global__ void __launch_bounds__(256, 2)
fa_kernel(const __half* __restrict__ Qu, const __half* __restrict__ Km,
          const float* __restrict__ M, const __half* __restrict__ V,
          float* __restrict__ Ctx)
{
    extern __shared__ __half fsm[];
    __half* Qf  = fsm;                       // [128][72]
    __half* KfB = fsm + 128 * 72;            // [2][64][72]
    __half* VfB = KfB + 2 * 64 * 72;         // [2][64][72]

    const int tid  = threadIdx.x;
    const int lane = tid & 31, w = tid >> 5;
    const int lq = lane >> 2, lr = lane & 3;
    const int aR = ((lane >> 3) & 1) * 8 + (lane & 7);
    const int aK = (lane >> 4) * 8;
    const int bR = (lane >> 4) * 8 + (lane & 7);
    const int bK = ((lane >> 3) & 1) * 8;
    const int z = blockIdx.y, b = z >> 3, h = z & 7;
    const int i0 = blockIdx.x * 128;
    const int r0 = i0 + w * 16 + lq;
    const int r1 = r0 + 8;

    const __half* Qb = Qu + ((size_t)(b * SS) + i0) * DD + h * DHH;
    const __half* Kb = Km + (size_t)(b * SS) * DD + h * DHH;
    const __half* Vb = V  + (size_t)(b * SS) * DD + h * DHH;
    const float* Mrow0 = M + ((size_t)z * SS + r0) * SS;
    const float* Mrow1 = M + ((size_t)z * SS + r1) * SS;

    // initial group: Q (128x64) + K0 + V0 (64x64 each)
#pragma unroll
    for (int t = 0; t < 4; t++) {
        int id = tid + t * 256;
        int row = id >> 3, ch = (id & 7) * 8;
        cpa16(&Qf[row * 72 + ch], &Qb[(size_t)row * DD + ch]);
    }
#pragma unroll
    for (int t = 0; t < 2; t++) {
        int id = tid + t * 256;
        int row = id >> 3, ch = (id & 7) * 8;
        cpa16(&KfB[row * 72 + ch], &Kb[(size_t)row * DD + ch]);
        cpa16(&VfB[row * 72 + ch], &Vb[(size_t)row * DD + ch]);
    }
    CPA_COMMIT();

    float acc[8][4] = {};
    float rm0 = -1e30f, rm1 = -1e30f, l0 = 0.f, l1 = 0.f;
    int buf = 0;

    for (int jt = 0; jt < SS; jt += 64) {
        // prefetch fp32 M band for this tile (consumed after the QK MMAs)
        float pv[8][4];
#pragma unroll
        for (int an = 0; an < 8; an++) {
#pragma unroll
            for (int e = 0; e < 2; e++) {
                int j = jt + an * 8 + 2 * lr + e;
                float p0, p1;
                if (j <= r0)          p0 = Mrow0[SS - 1 - r0 + j];
                else if (j == r0 + 1) p0 = 0.f;
                else                  p0 = Mrow0[SS + (j - r0 - 2)];
                if (j <= r1)          p1 = Mrow1[SS - 1 - r1 + j];
                else if (j == r1 + 1) p1 = 0.f;
                else                  p1 = Mrow1[SS + (j - r1 - 2)];
                pv[an][e] = p0; pv[an][2 + e] = p1;
            }
        }

        CPA_WAIT0();
        __syncthreads();           // all warps done with buf^1 reads + copies visible

        const __half* Kc = KfB + buf * (64 * 72);
        const __half* Vc = VfB + buf * (64 * 72);

        // kick off next tile's K/V copy into the other buffer
        if (jt + 64 < SS) {
            __half* Kn = KfB + (buf ^ 1) * (64 * 72);
            __half* Vn = VfB + (buf ^ 1) * (64 * 72);
#pragma unroll
            for (int t = 0; t < 2; t++) {
                int id = tid + t * 256;
                int row = id >> 3, ch = (id & 7) * 8;
                cpa16(&Kn[row * 72 + ch], &Kb[(size_t)(jt + 64 + row) * DD + ch]);
                cpa16(&Vn[row * 72 + ch], &Vb[(size_t)(jt + 64 + row) * DD + ch]);
            }
        }
        CPA_COMMIT();

        // S = (scaled Q) K^T  (warp: 16 rows x 64 j)
        float s[8][4] = {};
#pragma unroll
        for (int kb = 0; kb < 4; kb++) {
            uint32_t a[4], bb[4][4];
            ldsm4(a, &Qf[(w * 16 + aR) * 72 + kb * 16 + aK]);
#pragma unroll
            for (int np = 0; np < 4; np++)
                ldsm4(bb[np], &Kc[(np * 16 + bR) * 72 + kb * 16 + bK]);
#pragma unroll
            for (int an = 0; an < 8; an++)
                mma_f16(s[an], a,
                        bb[an >> 1][(an & 1) * 2], bb[an >> 1][(an & 1) * 2 + 1]);
        }

        // combine with pre-scaled pos scores, tile max
        float tm0 = -1e30f, tm1 = -1e30f;
#pragma unroll
        for (int an = 0; an < 8; an++) {
#pragma unroll
            for (int e = 0; e < 2; e++) {
                float s0 = s[an][e]     + pv[an][e];
                float s1 = s[an][2 + e] + pv[an][2 + e];
                s[an][e] = s0; s[an][2 + e] = s1;
                tm0 = fmaxf(tm0, s0); tm1 = fmaxf(tm1, s1);
            }
        }
        tm0 = fmaxf(tm0, __shfl_xor_sync(0xffffffffu, tm0, 1));
        tm0 = fmaxf(tm0, __shfl_xor_sync(0xffffffffu, tm0, 2));
        tm1 = fmaxf(tm1, __shfl_xor_sync(0xffffffffu, tm1, 1));
        tm1 = fmaxf(tm1, __shfl_xor_sync(0xffffffffu, tm1, 2));

        float nm0 = fmaxf(rm0, tm0), nm1 = fmaxf(rm1, tm1);
        float al0 = __expf(rm0 - nm0), al1 = __expf(rm1 - nm1);
        float sum0 = 0.f, sum1 = 0.f;
#pragma unroll
        for (int an = 0; an < 8; an++)
#pragma unroll
            for (int e = 0; e < 2; e++) {
                s[an][e]     = __expf(s[an][e]     - nm0); sum0 += s[an][e];
                s[an][2 + e] = __expf(s[an][2 + e] - nm1); sum1 += s[an][2 + e];
            }
        sum0 += __shfl_xor_sync(0xffffffffu, sum0, 1);
        sum0 += __shfl_xor_sync(0xffffffffu, sum0, 2);
        sum1 += __shfl_xor_sync(0xffffffffu, sum1, 1);
        sum1 += __shfl_xor_sync(0xffffffffu, sum1, 2);
        l0 = l0 * al0 + sum0; l1 = l1 * al1 + sum1;
        rm0 = nm0; rm1 = nm1;

#pragma unroll
        for (int an = 0; an < 8; an++) {
            acc[an][0] *= al0; acc[an][1] *= al0;
            acc[an][2] *= al1; acc[an][3] *= al1;
        }

        // O += P @ V ; P straight from registers (C-frag == A-frag layout)
#pragma unroll
        for (int jj = 0; jj < 4; jj++) {
            uint32_t a[4];
            a[0] = h2u(s[2*jj][0],     s[2*jj][1]);
            a[1] = h2u(s[2*jj][2],     s[2*jj][3]);
            a[2] = h2u(s[2*jj + 1][0], s[2*jj + 1][1]);
            a[3] = h2u(s[2*jj + 1][2], s[2*jj + 1][3]);
            uint32_t vv[4][4];
#pragma unroll
            for (int dp = 0; dp < 4; dp++)
                ldsm4t(vv[dp], &Vc[(jj * 16 + aR) * 72 + dp * 16 + aK]);
#pragma unroll
            for (int dn = 0; dn < 8; dn++)
                mma_f16(acc[dn], a,
                        vv[dn >> 1][(dn & 1) * 2], vv[dn >> 1][(dn & 1) * 2 + 1]);
        }
        buf ^= 1;
    }

    float inv0 = 1.f / l0, inv1 = 1.f / l1;
#pragma unroll
    for (int dn = 0; dn < 8; dn++) {
        int col = dn * 8 + 2 * lr;
        float2 v0 = make_float2(acc[dn][0] * inv0, acc[dn][1] * inv0);
        float2 v1 = make_float2(acc[dn][2] * inv1, acc[dn][3] * inv1);
        *(float2*)&Ctx[(size_t)(b * SS + r0) * DD + h * DHH + col] = v0;
        *(float2*)&Ctx[(size_t)(b * SS + r1) * DD + h * DHH + col] = v1;
    }
}

// ---------------- launcher ------------------------------------------------------
extern "C" void kernel_launch(void* const* d_in, const int* in_sizes, int n_in,
                              void* d_out, int out_size)
{
    (void)in_sizes; (void)n_in; (void)out_size;
    const float* query = (const float*)d_in[0];
    const float* key   = (const float*)d_in[1];
    const float* value = (const float*)d_in[2];
    const float* pose  = (const float*)d_in[3];
    const float* Wq = (const float*)d_in[4];
    const float* bq = (const float*)d_in[5];
    const float* Wk = (const float*)d_in[6];
    const float* bk = (const float*)d_in[7];
    const float* Wv = (const float*)d_in[8];
    const float* bv = (const float*)d_in[9];
    const float* Wp = (const float*)d_in[10];
    const float* ub = (const float*)d_in[11];
    const float* vb = (const float*)d_in[12];
    const float* Wo = (const float*)d_in[13];
    const float* bo = (const float*)d_in[14];
    float* out = (float*)d_out;

    const float scale = 0.04419417382415922f;   // 1/sqrt(512)

    __half *qu, *qv, *kk, *vv, *pp;
    float *M, *ctx;
    cudaGetSymbolAddress((void**)&qu,  g_qu);
    cudaGetSymbolAddress((void**)&qv,  g_qv);
    cudaGetSymbolAddress((void**)&kk,  g_k);
    cudaGetSymbolAddress((void**)&vv,  g_v);
    cudaGetSymbolAddress((void**)&pp,  g_p);
    cudaGetSymbolAddress((void**)&M,   g_M);
    cudaGetSymbolAddress((void**)&ctx, g_ctx);

    cudaFuncSetAttribute(fa_kernel, cudaFuncAttributeMaxDynamicSharedMemorySize,
                         FA_SMEM);

    // merged 4 input projections (fp16 outputs; qu/qv pre-scaled)
    ProjArgs pa;
    pa.s[0] = {query, Wq, bq, ub, vb, qu, qv, 1, scale};
    pa.s[1] = {key,   Wk, bk, nullptr, nullptr, kk, nullptr, 1, 1.f};
    pa.s[2] = {value, Wv, bv, nullptr, nullptr, vv, nullptr, 1, 1.f};
    pa.s[3] = {pose,  Wp, nullptr, nullptr, nullptr, pp, nullptr, 1, 1.f};
    dim3 pg(DD / 128, MTOT / 128, 4);      // (4, 64, 4)
    proj_kernel<<<pg, 256>>>(pa);

    dim3 sg(SS / 128, SS / 128, BH);       // (8,8,64)
    score_kernel<<<sg, 256>>>(qv, pp, M);

    dim3 fg(SS / 128, BH);                 // (8, 64)
    fa_kernel<<<fg, 256, FA_SMEM>>>(qu, kk, M, vv, ctx);

    // output projection (fp32 out)
    ProjArgs po;
    po.s[0] = {ctx, Wo, bo, nullptr, nullptr, out, nullptr, 0, 1.f};
    po.s[1] = po.s[0]; po.s[2] = po.s[0]; po.s[3] = po.s[0];
    dim3 pg1(DD / 128, MTOT / 128, 1);     // (4, 64, 1)
    proj_kernel<<<pg1, 256>>>(po);
}

// round 13
// speedup vs baseline: 1.2413x; 1.0481x over previous
#include <cuda_runtime.h>
#include <cuda_fp16.h>
#include <cstdint>

#define BB 8
#define SS 1024
#define DD 512
#define HH 8
#define DHH 64
#define MTOT (BB*SS)   // 8192
#define BH   (BB*HH)   // 64

// ---------------- scratch (__device__ globals) ---------------------------------
__device__ __half g_x16[4][MTOT*DD];            // fp16 copies of query/key/value/pos
__device__ __half g_w16[5][DD*DD];              // fp16 copies of Wq,Wk,Wv,Wp,Wo
__device__ __half g_qu[MTOT*DD];                // scale*(q + u_bias)  (fp16)
__device__ __half g_qv[MTOT*DD];                // scale*(q + v_bias)  (fp16)
__device__ __half g_k [MTOT*DD];
__device__ __half g_v [MTOT*DD];
__device__ __half g_p [MTOT*DD];
__device__ float  g_M [BH*SS*SS];               // pre-scaled pos scores (fp32)
__device__ __half g_ctx[MTOT*DD];               // attention output (fp16)

// ---------------- helpers -------------------------------------------------------
__device__ __forceinline__ uint32_t h2u(float a, float b) {
    __half2 h = __floats2half2_rn(a, b);
    return *reinterpret_cast<uint32_t*>(&h);
}
__device__ __forceinline__ uint4 pack8(float4 a, float4 b) {
    uint4 r;
    r.x = h2u(a.x, a.y); r.y = h2u(a.z, a.w);
    r.z = h2u(b.x, b.y); r.w = h2u(b.z, b.w);
    return r;
}
__device__ __forceinline__ void ldsm4(uint32_t* r, const __half* p) {
    uint32_t a = (uint32_t)__cvta_generic_to_shared(p);
    asm volatile("ldmatrix.sync.aligned.m8n8.x4.shared.b16 {%0,%1,%2,%3}, [%4];"
                 : "=r"(r[0]), "=r"(r[1]), "=r"(r[2]), "=r"(r[3]) : "r"(a));
}
__device__ __forceinline__ void ldsm4t(uint32_t* r, const __half* p) {
    uint32_t a = (uint32_t)__cvta_generic_to_shared(p);
    asm volatile("ldmatrix.sync.aligned.m8n8.x4.trans.shared.b16 {%0,%1,%2,%3}, [%4];"
                 : "=r"(r[0]), "=r"(r[1]), "=r"(r[2]), "=r"(r[3]) : "r"(a));
}
__device__ __forceinline__ void mma_f16(float c[4], const uint32_t a[4],
                                        uint32_t b0, uint32_t b1)
{
    asm volatile(
        "mma.sync.aligned.m16n8k16.row.col.f32.f16.f16.f32 "
        "{%0,%1,%2,%3}, {%4,%5,%6,%7}, {%8,%9}, {%0,%1,%2,%3};"
        : "+f"(c[0]), "+f"(c[1]), "+f"(c[2]), "+f"(c[3])
        : "r"(a[0]), "r"(a[1]), "r"(a[2]), "r"(a[3]), "r"(b0), "r"(b1));
}
__device__ __forceinline__ void cpa16(__half* dst, const __half* src) {
    uint32_t d = (uint32_t)__cvta_generic_to_shared(dst);
    asm volatile("cp.async.ca.shared.global [%0], [%1], 16;" :: "r"(d), "l"(src));
}
#define CPA_COMMIT() asm volatile("cp.async.commit_group;")
#define CPA_WAIT0()  asm volatile("cp.async.wait_group 0;")

// ---------------- kernel 0: fp32 -> fp16 bulk convert ---------------------------
struct CvtEnt { const float* s; __half* d; int n; };
struct CvtArgs { CvtEnt e[9]; };

__global__ void __launch_bounds__(256)
cvt_kernel(CvtArgs a)
{
    CvtEnt E = a.e[blockIdx.y];
    int i = (blockIdx.x * 256 + threadIdx.x) * 8;
    if (i < E.n) {
        float4 x = *(const float4*)&E.s[i];
        float4 y = *(const float4*)&E.s[i + 4];
        *(uint4*)&E.d[i] = pack8(x, y);
    }
}

// ---------------- kernel 1: projection GEMM (fp16 in, cp.async ping-pong) -------
struct ProjSet {
    const __half *A, *W;
    const float *bias, *ex0, *ex1;
    void *out0, *out1;     // __half* if h_out else float*
    int h_out;
    float post;
};
struct ProjArgs { ProjSet s[4]; };

#define BFS 136   // W tile row stride in halves

__global__ void __launch_bounds__(256, 2)
proj_kernel(ProjArgs args)
{
    __shared__ __align__(16) __half Af[2][128 * 40];    // A tile [m][k]
    __shared__ __align__(16) __half Bf[2][32 * BFS];    // W tile [k][n]
    const ProjSet ps = args.s[blockIdx.z];
    const __half* __restrict__ A = ps.A;
    const __half* __restrict__ W = ps.W;

    const int tid  = threadIdx.x;
    const int lane = tid & 31, w = tid >> 5;
    const int wm = w & 1, wn = w >> 1;            // 2 x 4 warps, warp tile 64x32
    const int m_w = wm * 64, n_w = wn * 32;
    const int m0 = blockIdx.y * 128, n0 = blockIdx.x * 128;
    const int lq = lane >> 2, lr = lane & 3;
    const int aR = ((lane >> 3) & 1) * 8 + (lane & 7);
    const int aK = (lane >> 4) * 8;

    // cp.async loader mapping (512 16B chunks per tile, 2 per thread)
    const int a_row = tid >> 2, a_ch = (tid & 3) * 8;      // A: 128 rows x 64B
    const int b_row = tid >> 4, b_ch = (tid & 15) * 8;     // W: 32 rows x 256B

    // prologue: tile 0 -> buffer 0
#pragma unroll
    for (int t = 0; t < 2; t++) {
        int id = tid + t * 256;
        int ar = id >> 2,  ac = (id & 3) * 8;
        int br = id >> 4,  bc = (id & 15) * 8;
        cpa16(&Af[0][ar * 40 + ac],  &A[(size_t)(m0 + ar) * DD + ac]);
        cpa16(&Bf[0][br * BFS + bc], &W[(size_t)br * DD + n0 + bc]);
    }
    CPA_COMMIT();
    (void)a_row; (void)a_ch; (void)b_row; (void)b_ch;

    float acc[4][4][4] = {};
    int cur = 0;

    for (int k0 = 0; k0 < DD; k0 += 32) {
        CPA_WAIT0();
        __syncthreads();
        const bool has_next = (k0 + 32 < DD);
        if (has_next) {
            int nb = cur ^ 1;
#pragma unroll
            for (int t = 0; t < 2; t++) {
                int id = tid + t * 256;
                int ar = id >> 2,  ac = (id & 3) * 8;
                int br = id >> 4,  bc = (id & 15) * 8;
                cpa16(&Af[nb][ar * 40 + ac],
                      &A[(size_t)(m0 + ar) * DD + k0 + 32 + ac]);
                cpa16(&Bf[nb][br * BFS + bc],
                      &W[(size_t)(k0 + 32 + br) * DD + n0 + bc]);
            }
        }
        CPA_COMMIT();

#pragma unroll
        for (int kb = 0; kb < 2; kb++) {
            uint32_t a[4][4], bb[2][4];
#pragma unroll
            for (int ma = 0; ma < 4; ma++)
                ldsm4(a[ma], &Af[cur][(m_w + ma * 16 + aR) * 40 + kb * 16 + aK]);
#pragma unroll
            for (int np = 0; np < 2; np++)
                ldsm4t(bb[np], &Bf[cur][(kb * 16 + aR) * BFS + n_w + np * 16 + aK]);
#pragma unroll
            for (int ma = 0; ma < 4; ma++)
#pragma unroll
                for (int an = 0; an < 4; an++)
                    mma_f16(acc[ma][an], a[ma],
                            bb[an >> 1][(an & 1) * 2], bb[an >> 1][(an & 1) * 2 + 1]);
        }
        cur ^= 1;
    }

#pragma unroll
    for (int ma = 0; ma < 4; ma++) {
#pragma unroll
        for (int an = 0; an < 4; an++) {
#pragma unroll
            for (int half = 0; half < 2; half++) {
                int row = m0 + m_w + ma * 16 + lq + half * 8;
                int col = n0 + n_w + an * 8 + lr * 2;
                float v0 = acc[ma][an][half * 2 + 0];
                float v1 = acc[ma][an][half * 2 + 1];
                if (ps.bias) { v0 += ps.bias[col]; v1 += ps.bias[col + 1]; }
                if (ps.out0) {
                    float e0 = ps.ex0 ? ps.ex0[col] : 0.f;
                    float e1 = ps.ex0 ? ps.ex0[col + 1] : 0.f;
                    float o0 = (v0 + e0) * ps.post, o1 = (v1 + e1) * ps.post;
                    if (ps.h_out)
                        *(uint32_t*)&((__half*)ps.out0)[(size_t)row * DD + col] = h2u(o0, o1);
                    else
                        *(float2*)&((float*)ps.out0)[(size_t)row * DD + col] =
                            make_float2(o0, o1);
                }
                if (ps.out1) {
                    float e0 = ps.ex1 ? ps.ex1[col] : 0.f;
                    float e1 = ps.ex1 ? ps.ex1[col + 1] : 0.f;
                    *(uint32_t*)&((__half*)ps.out1)[(size_t)row * DD + col] =
                        h2u((v0 + e0) * ps.post, (v1 + e1) * ps.post);
                }
            }
        }
    }
}

// ---------------- kernel 2: pos-score GEMM (M), fp16 in / fp32 out --------------
__global__ void __launch_bounds__(256, 2)
score_kernel(const __half* __restrict__ Qm, const __half* __restrict__ Km,
             float* __restrict__ Out)
{
    __shared__ __align__(16) __half Qf[128 * 72];    // [i][d]
    __shared__ __align__(16) __half Pf[128 * 72];    // [j][d]
    const int tid  = threadIdx.x;
    const int lane = tid & 31, w = tid >> 5;
    const int wm = w & 1, wn = w >> 1;
    const int m_w = wm * 64, n_w = wn * 32;
    const int z = blockIdx.z, b = z >> 3, h = z & 7;
    const int i0 = blockIdx.y * 128, j0 = blockIdx.x * 128;
    const int lq = lane >> 2, lr = lane & 3;
    const int aR = ((lane >> 3) & 1) * 8 + (lane & 7);
    const int aK = (lane >> 4) * 8;
    const int bR = (lane >> 4) * 8 + (lane & 7);
    const int bK = ((lane >> 3) & 1) * 8;
    const __half* Qb = Qm + (size_t)(b * SS) * DD + h * DHH;
    const __half* Kb = Km + (size_t)(b * SS) * DD + h * DHH;

#pragma unroll
    for (int t = 0; t < 4; t++) {
        int id = tid + t * 256;
        int row = id >> 3, col = (id & 7) * 8;
        cpa16(&Qf[row * 72 + col], &Qb[(size_t)(i0 + row) * DD + col]);
        cpa16(&Pf[row * 72 + col], &Kb[(size_t)(j0 + row) * DD + col]);
    }
    CPA_COMMIT();
    CPA_WAIT0();
    __syncthreads();

    float acc[4][4][4] = {};
#pragma unroll
    for (int kb = 0; kb < 4; kb++) {
        uint32_t a[4][4], bb[2][4];
#pragma unroll
        for (int ma = 0; ma < 4; ma++)
            ldsm4(a[ma], &Qf[(m_w + ma * 16 + aR) * 72 + kb * 16 + aK]);
#pragma unroll
        for (int np = 0; np < 2; np++)
            ldsm4(bb[np], &Pf[(n_w + np * 16 + bR) * 72 + kb * 16 + bK]);
#pragma unroll
        for (int ma = 0; ma < 4; ma++)
#pragma unroll
            for (int an = 0; an < 4; an++)
                mma_f16(acc[ma][an], a[ma],
                        bb[an >> 1][(an & 1) * 2], bb[an >> 1][(an & 1) * 2 + 1]);
    }

#pragma unroll
    for (int ma = 0; ma < 4; ma++) {
#pragma unroll
        for (int an = 0; an < 4; an++) {
#pragma unroll
            for (int half = 0; half < 2; half++) {
                int row = i0 + m_w + ma * 16 + lq + half * 8;
                int col = j0 + n_w + an * 8 + lr * 2;
                float2 vv = make_float2(acc[ma][an][half * 2 + 0],
                                        acc[ma][an][half * 2 + 1]);
                *(float2*)&Out[((size_t)z * SS + row) * SS + col] = vv;
            }
        }
    }
}

// ---------------- kernel 3: fused QK^T + shift + softmax + PV -------------------
// 256 thr = 8 warps; block owns 128 q-rows. cp.async double-buffered K/V.
#define FA_SMEM ((128*72 + 2*64*72 + 2*64*72) * 2)   // bytes (55296)
__global__ void __launch_bounds__(256, 2)
fa_kernel(const __half* __restrict__ Qu, const __half* __restrict__ Km,
          const float* __restrict__ M, const __half* __restrict__ V,
          __half* __restrict__ Ctx)
{
    extern __shared__ __half fsm[];
    __half* Qf  = fsm;                       // [128][72]
    __half* KfB = fsm + 128 * 72;            // [2][64][72]
    __half* VfB = KfB + 2 * 64 * 72;         // [2][64][72]

    const int tid  = threadIdx.x;
    const int lane = tid & 31, w = tid >> 5;
    const int lq = lane >> 2, lr = lane & 3;
    const int aR = ((lane >> 3) & 1) * 8 + (lane & 7);
    const int aK = (lane >> 4) * 8;
    const int bR = (lane >> 4) * 8 + (lane & 7);
    const int bK = ((lane >> 3) & 1) * 8;
    const int z = blockIdx.y, b = z >> 3, h = z & 7;
    const int i0 = blockIdx.x * 128;
    const int r0 = i0 + w * 16 + lq;
    const int r1 = r0 + 8;

    const __half* Qb = Qu + ((size_t)(b * SS) + i0) * DD + h * DHH;
    const __half* Kb = Km + (size_t)(b * SS) * DD + h * DHH;
    const __half* Vb = V  + (size_t)(b * SS) * DD + h * DHH;
    const float* Mrow0 = M + ((size_t)z * SS + r0) * SS;
    const float* Mrow1 = M + ((size_t)z * SS + r1) * SS;

    // initial group: Q (128x64) + K0 + V0 (64x64 each)
#pragma unroll
    for (int t = 0; t < 4; t++) {
        int id = tid + t * 256;
        int row = id >> 3, ch = (id & 7) * 8;
        cpa16(&Qf[row * 72 + ch], &Qb[(size_t)row * DD + ch]);
    }
#pragma unroll
    for (int t = 0; t < 2; t++) {
        int id = tid + t * 256;
        int row = id >> 3, ch = (id & 7) * 8;
        cpa16(&KfB[row * 72 + ch], &Kb[(size_t)row * DD + ch]);
        cpa16(&VfB[row * 72 + ch], &Vb[(size_t)row * DD + ch]);
    }
    CPA_COMMIT();

    float acc[8][4] = {};
    float rm0 = -1e30f, rm1 = -1e30f, l0 = 0.f, l1 = 0.f;
    int buf = 0;

    for (int jt = 0; jt < SS; jt += 64) {
        // prefetch fp32 M band for this tile (consumed after the QK MMAs)
        float pv[8][4];
#pragma unroll
        for (int an = 0; an < 8; an++) {
#pragma unroll
            for (int e = 0; e < 2; e++) {
                int j = jt + an * 8 + 2 * lr + e;
                float p0, p1;
                if (j <= r0)          p0 = Mrow0[SS - 1 - r0 + j];
                else if (j == r0 + 1) p0 = 0.f;
                else                  p0 = Mrow0[SS + (j - r0 - 2)];
                if (j <= r1)          p1 = Mrow1[SS - 1 - r1 + j];
                else if (j == r1 + 1) p1 = 0.f;
                else                  p1 = Mrow1[SS + (j - r1 - 2)];
                pv[an][e] = p0; pv[an][2 + e] = p1;
            }
        }

        CPA_WAIT0();
        __syncthreads();

        const __half* Kc = KfB + buf * (64 * 72);
        const __half* Vc = VfB + buf * (64 * 72);

        if (jt + 64 < SS) {
            __half* Kn = KfB + (buf ^ 1) * (64 * 72);
            __half* Vn = VfB + (buf ^ 1) * (64 * 72);
#pragma unroll
            for (int t = 0; t < 2; t++) {
                int id = tid + t * 256;
                int row = id >> 3, ch = (id & 7) * 8;
                cpa16(&Kn[row * 72 + ch], &Kb[(size_t)(jt + 64 + row) * DD + ch]);
                cpa16(&Vn[row * 72 + ch], &Vb[(size_t)(jt + 64 + row) * DD + ch]);
            }
        }
        CPA_COMMIT();

        // S = (scaled Q) K^T
        float s[8][4] = {};
#pragma unroll
        for (int kb = 0; kb < 4; kb++) {
            uint32_t a[4], bb[4][4];
            ldsm4(a, &Qf[(w * 16 + aR) * 72 + kb * 16 + aK]);
#pragma unroll
            for (int np = 0; np < 4; np++)
                ldsm4(bb[np], &Kc[(np * 16 + bR) * 72 + kb * 16 + bK]);
#pragma unroll
            for (int an = 0; an < 8; an++)
                mma_f16(s[an], a,
                        bb[an >> 1][(an & 1) * 2], bb[an >> 1][(an & 1) * 2 + 1]);
        }

        // combine with pos scores, tile max
        float tm0 = -1e30f, tm1 = -1e30f;
#pragma unroll
        for (int an = 0; an < 8; an++) {
#pragma unroll
            for (int e = 0; e < 2; e++) {
                float s0 = s[an][e]     + pv[an][e];
                float s1 = s[an][2 + e] + pv[an][2 + e];
                s[an][e] = s0; s[an][2 + e] = s1;
                tm0 = fmaxf(tm0, s0); tm1 = fmaxf(tm1, s1);
            }
        }
        tm0 = fmaxf(tm0, __shfl_xor_sync(0xffffffffu, tm0, 1));
        tm0 = fmaxf(tm0, __shfl_xor_sync(0xffffffffu, tm0, 2));
        tm1 = fmaxf(tm1, __shfl_xor_sync(0xffffffffu, tm1, 1));
        tm1 = fmaxf(tm1, __shfl_xor_sync(0xffffffffu, tm1, 2));

        float nm0 = fmaxf(rm0, tm0), nm1 = fmaxf(rm1, tm1);
        float al0 = __expf(rm0 - nm0), al1 = __expf(rm1 - nm1);
        float sum0 = 0.f, sum1 = 0.f;
#pragma unroll
        for (int an = 0; an < 8; an++)
#pragma unroll
            for (int e = 0; e < 2; e++) {
                s[an][e]     = __expf(s[an][e]     - nm0); sum0 += s[an][e];
                s[an][2 + e] = __expf(s[an][2 + e] - nm1); sum1 += s[an][2 + e];
            }
        sum0 += __shfl_xor_sync(0xffffffffu, sum0, 1);
        sum0 += __shfl_xor_sync(0xffffffffu, sum0, 2);
        sum1 += __shfl_xor_sync(0xffffffffu, sum1, 1);
        sum1 += __shfl_xor_sync(0xffffffffu, sum1, 2);
        l0 = l0 * al0 + sum0; l1 = l1 * al1 + sum1;
        rm0 = nm0; rm1 = nm1;

#pragma unroll
        for (int an = 0; an < 8; an++) {
            acc[an][0] *= al0; acc[an][1] *= al0;
            acc[an][2] *= al1; acc[an][3] *= al1;
        }

        // O += P @ V
#pragma unroll
        for (int jj = 0; jj < 4; jj++) {
            uint32_t a[4];
            a[0] = h2u(s[2*jj][0],     s[2*jj][1]);
            a[1] = h2u(s[2*jj][2],     s[2*jj][3]);
            a[2] = h2u(s[2*jj + 1][0], s[2*jj + 1][1]);
            a[3] = h2u(s[2*jj + 1][2], s[2*jj + 1][3]);
            uint32_t vv[4][4];
#pragma unroll
            for (int dp = 0; dp < 4; dp++)
                ldsm4t(vv[dp], &Vc[(jj * 16 + aR) * 72 + dp * 16 + aK]);
#pragma unroll
            for (int dn = 0; dn < 8; dn++)
                mma_f16(acc[dn], a,
                        vv[dn >> 1][(dn & 1) * 2], vv[dn >> 1][(dn & 1) * 2 + 1]);
        }
        buf ^= 1;
    }

    float inv0 = 1.f / l0, inv1 = 1.f / l1;
#pragma unroll
    for (int dn = 0; dn < 8; dn++) {
        int col = dn * 8 + 2 * lr;
        *(uint32_t*)&Ctx[(size_t)(b * SS + r0) * DD + h * DHH + col] =
            h2u(acc[dn][0] * inv0, acc[dn][1] * inv0);
        *(uint32_t*)&Ctx[(size_t)(b * SS + r1) * DD + h * DHH + col] =
            h2u(acc[dn][2] * inv1, acc[dn][3] * inv1);
    }
}

// ---------------- launcher ------------------------------------------------------
extern "C" void kernel_launch(void* const* d_in, const int* in_sizes, int n_in,
                              void* d_out, int out_size)
{
    (void)in_sizes; (void)n_in; (void)out_size;
    const float* query = (const float*)d_in[0];
    const float* key   = (const float*)d_in[1];
    const float* value = (const float*)d_in[2];
    const float* pose  = (const float*)d_in[3];
    const float* Wq = (const float*)d_in[4];
    const float* bq = (const float*)d_in[5];
    const float* Wk = (const float*)d_in[6];
    const float* bk = (const float*)d_in[7];
    const float* Wv = (const float*)d_in[8];
    const float* bv = (const float*)d_in[9];
    const float* Wp = (const float*)d_in[10];
    const float* ub = (const float*)d_in[11];
    const float* vb = (const float*)d_in[12];
    const float* Wo = (const float*)d_in[13];
    const float* bo = (const float*)d_in[14];
    float* out = (float*)d_out;

    const float scale = 0.04419417382415922f;   // 1/sqrt(512)

    __half *x16, *w16, *qu, *qv, *kk, *vv, *pp, *ctx;
    float *M;
    cudaGetSymbolAddress((void**)&x16, g_x16);
    cudaGetSymbolAddress((void**)&w16, g_w16);
    cudaGetSymbolAddress((void**)&qu,  g_qu);
    cudaGetSymbolAddress((void**)&qv,  g_qv);
    cudaGetSymbolAddress((void**)&kk,  g_k);
    cudaGetSymbolAddress((void**)&vv,  g_v);
    cudaGetSymbolAddress((void**)&pp,  g_p);
    cudaGetSymbolAddress((void**)&M,   g_M);
    cudaGetSymbolAddress((void**)&ctx, g_ctx);

    cudaFuncSetAttribute(fa_kernel, cudaFuncAttributeMaxDynamicSharedMemorySize,
                         FA_SMEM);

    const int NX = MTOT * DD;      // 4194304
    const int NW = DD * DD;        // 262144

    // convert inputs + weights to fp16
    CvtArgs ca;
    ca.e[0] = {query, x16 + 0 * (size_t)NX, NX};
    ca.e[1] = {key,   x16 + 1 * (size_t)NX, NX};
    ca.e[2] = {value, x16 + 2 * (size_t)NX, NX};
    ca.e[3] = {pose,  x16 + 3 * (size_t)NX, NX};
    ca.e[4] = {Wq, w16 + 0 * (size_t)NW, NW};
    ca.e[5] = {Wk, w16 + 1 * (size_t)NW, NW};
    ca.e[6] = {Wv, w16 + 2 * (size_t)NW, NW};
    ca.e[7] = {Wp, w16 + 3 * (size_t)NW, NW};
    ca.e[8] = {Wo, w16 + 4 * (size_t)NW, NW};
    dim3 cg(NX / 8 / 256, 9);              // (2048, 9)
    cvt_kernel<<<cg, 256>>>(ca);

    // merged 4 input projections (fp16 outputs; qu/qv pre-scaled)
    ProjArgs pa;
    pa.s[0] = {x16 + 0 * (size_t)NX, w16 + 0 * (size_t)NW, bq, ub, vb, qu, qv, 1, scale};
    pa.s[1] = {x16 + 1 * (size_t)NX, w16 + 1 * (size_t)NW, bk, nullptr, nullptr, kk, nullptr, 1, 1.f};
    pa.s[2] = {x16 + 2 * (size_t)NX, w16 + 2 * (size_t)NW, bv, nullptr, nullptr, vv, nullptr, 1, 1.f};
    pa.s[3] = {x16 + 3 * (size_t)NX, w16 + 3 * (size_t)NW, nullptr, nullptr, nullptr, pp, nullptr, 1, 1.f};
    dim3 pg(DD / 128, MTOT / 128, 4);      // (4, 64, 4)
    proj_kernel<<<pg, 256>>>(pa);

    dim3 sg(SS / 128, SS / 128, BH);       // (8,8,64)
    score_kernel<<<sg, 256>>>(qv, pp, M);

    dim3 fg(SS / 128, BH);                 // (8, 64)
    fa_kernel<<<fg, 256, FA_SMEM>>>(qu, kk, M, vv, ctx);

    // output projection (fp32 out)
    ProjArgs po;
    po.s[0] = {ctx, w16 + 4 * (size_t)NW, bo, nullptr, nullptr, out, nullptr, 0, 1.f};
    po.s[1] = po.s[0]; po.s[2] = po.s[0]; po.s[3] = po.s[0];
    dim3 pg1(DD / 128, MTOT / 128, 1);     // (4, 64, 1)
    proj_kernel<<<pg1, 256>>>(po);
}